// round 2
// baseline (speedup 1.0000x reference)
#include <cuda_runtime.h>
#include <cstdint>

// Masked row-wise cumulative sum:
//   out[r, :] = cumsum(x[r, :] * mask[r, :])    (scan along the contiguous axis)
// x: float32 [M, N], out: float32 [M, N], M = 4096, N = 32768.
// mask dtype on the wire is ambiguous (bool may arrive as u8, i32, or f32 0/1)
// -> detect it from the data, deterministically, inside the graph.

#ifndef CUMSUM_N
#define CUMSUM_N 32768
#endif

#define TPB 1024          // threads per block
#define VEC 4             // elements per thread per chunk
#define CHUNK (TPB * VEC) // 4096 elements per chunk

// 1 = mask elements are 4-byte words (int32 or float32 0/1; truth = word != 0)
// 0 = mask elements are 1-byte      (uint8 bool;           truth = byte != 0)
__device__ int g_mask_word_mode;

__global__ void detect_mask_kernel(const unsigned* __restrict__ mask_words)
{
    __shared__ int s_found_u8;
    if (threadIdx.x == 0) s_found_u8 = 0;
    __syncthreads();

    // sample 4096 words (16 KB) — safe under every candidate encoding
    int bad = 0;
    #pragma unroll
    for (int i = 0; i < 4; i++) {
        unsigned w = mask_words[threadIdx.x + i * TPB];
        // words a 4-byte 0/1 encoding can produce: 0, 1 (int32), 0x3F800000 (float 1.0)
        if (w != 0u && w != 1u && w != 0x3F800000u) bad = 1;
    }
    if (__syncthreads_or(bad)) {
        if (threadIdx.x == 0) g_mask_word_mode = 0;   // random bytes -> uint8
    } else {
        if (threadIdx.x == 0) g_mask_word_mode = 1;   // clean words  -> 4-byte
    }
}

__global__ __launch_bounds__(TPB, 2)
void masked_cumsum_row_kernel(const float* __restrict__ x,
                              const void* __restrict__ mask,
                              float* __restrict__ out,
                              int n_cols)
{
    const int row  = blockIdx.x;
    const size_t base = (size_t)row * (size_t)n_cols;

    const int tid  = threadIdx.x;
    const int lane = tid & 31;
    const int wid  = tid >> 5;

    const int word_mode = g_mask_word_mode;   // uniform; L1-resident after first block

    __shared__ float s_warp[TPB / 32];
    __shared__ float s_total;

    float carry = 0.0f;

    #pragma unroll 1
    for (int c = 0; c < n_cols; c += CHUNK) {
        const size_t off = base + (size_t)c + (size_t)tid * VEC;

        float4 xv = *reinterpret_cast<const float4*>(x + off);

        unsigned m0, m1, m2, m3;
        if (word_mode) {
            uint4 mv = *reinterpret_cast<const uint4*>((const unsigned*)mask + off);
            m0 = mv.x; m1 = mv.y; m2 = mv.z; m3 = mv.w;
        } else {
            uchar4 mv = *reinterpret_cast<const uchar4*>((const uint8_t*)mask + off);
            m0 = mv.x; m1 = mv.y; m2 = mv.z; m3 = mv.w;
        }

        float v0 = m0 ? xv.x : 0.0f;
        float v1 = m1 ? xv.y : 0.0f;
        float v2 = m2 ? xv.z : 0.0f;
        float v3 = m3 ? xv.w : 0.0f;

        // thread-local inclusive scan of 4
        float s0 = v0;
        float s1 = s0 + v1;
        float s2 = s1 + v2;
        float s3 = s2 + v3;

        // warp inclusive scan of per-thread totals
        float t = s3;
        #pragma unroll
        for (int d = 1; d < 32; d <<= 1) {
            float nv = __shfl_up_sync(0xffffffffu, t, d);
            if (lane >= d) t += nv;
        }
        const float thread_excl = t - s3;

        if (lane == 31) s_warp[wid] = t;
        __syncthreads();

        // warp 0 scans the 32 warp totals
        if (wid == 0) {
            float w  = s_warp[lane];
            float wt = w;
            #pragma unroll
            for (int d = 1; d < 32; d <<= 1) {
                float nv = __shfl_up_sync(0xffffffffu, wt, d);
                if (lane >= d) wt += nv;
            }
            s_warp[lane] = wt - w;
            if (lane == 31) s_total = wt;
        }
        __syncthreads();

        const float offv = carry + s_warp[wid] + thread_excl;

        float4 o;
        o.x = s0 + offv;
        o.y = s1 + offv;
        o.z = s2 + offv;
        o.w = s3 + offv;
        *reinterpret_cast<float4*>(out + off) = o;

        carry += s_total;
        __syncthreads();
    }
}

extern "C" void kernel_launch(void* const* d_in, const int* in_sizes, int n_in,
                              void* d_out, int out_size)
{
    const float* x    = (const float*)d_in[0];
    const void*  mask = d_in[1];
    float*       out  = (float*)d_out;

    const int n_cols = CUMSUM_N;
    const int n_rows = in_sizes[0] / n_cols;   // 4096

    detect_mask_kernel<<<1, TPB>>>((const unsigned*)mask);
    masked_cumsum_row_kernel<<<n_rows, TPB>>>(x, mask, out, n_cols);
}